// round 1
// baseline (speedup 1.0000x reference)
#include <cuda_runtime.h>

// Hausdorff distance, batched N=8, grid 96x96.
// haus[s] = max(directed(A\B -> B), directed(B\A -> A)), out = mean over s.
// directed(src -> tgt) = max_{p in src} min_{q in tgt} ||p-q||, coords (i/96, j/96).
// Exact integer EDT (separable): row sweep for min |dj|, column min of (di^2 + rd^2).

#define HD 96
#define WD 96
#define HW (HD * WD)

__device__ float g_dir[64];  // [sample*2 + dir]

__global__ void __launch_bounds__(256) hausdorff_dir_kernel(
    const float* __restrict__ pred, const float* __restrict__ targ) {
    __shared__ unsigned char s_tgt[HW];
    __shared__ unsigned char s_src[HW];
    __shared__ unsigned short s_rd2[HW];   // squared row-distance (sentinel 200^2=40000)
    __shared__ int s_red[256];
    __shared__ int s_anyTgt;

    const int s   = blockIdx.x;
    const int dir = blockIdx.y;           // 0: tgt=B, src=A&~B ; 1: tgt=A, src=B&~A
    const int tid = threadIdx.x;

    const float* __restrict__ P = pred + s * HW;
    const float* __restrict__ T = targ + s * HW;

    if (tid == 0) s_anyTgt = 0;

    // Phase 1: build masks (coalesced loads)
    for (int p = tid; p < HW; p += 256) {
        bool a = P[p] > 0.5f;   // round(x) > 0.5  <=>  x > 0.5 for x in [0,1)
        bool b = T[p] > 0.5f;
        bool tg = dir ? a : b;
        bool sr = dir ? (b && !a) : (a && !b);
        s_tgt[p] = (unsigned char)tg;
        s_src[p] = (unsigned char)sr;
    }
    __syncthreads();

    // Phase 2: per-row 1D distance (two sweeps), thread i owns row i
    if (tid < HD) {
        const int base = tid * WD;
        int d = 1000, any = 0;
        for (int j = 0; j < WD; j++) {
            if (s_tgt[base + j]) { d = 0; any = 1; } else d++;
            s_rd2[base + j] = (unsigned short)min(d, 200);
        }
        d = 1000;
        for (int j = WD - 1; j >= 0; j--) {
            if (s_tgt[base + j]) d = 0; else d++;
            int v = min((int)s_rd2[base + j], min(d, 200));
            s_rd2[base + j] = (unsigned short)(v * v);
        }
        if (any) atomicOr(&s_anyTgt, 1);
    }
    __syncthreads();

    // Phase 3: column pass fused with max-reduction over source pixels only.
    // d2(i,j) = min_{i'} (i-i')^2 + rd2(i',j). Sentinel rows (40000) can never win
    // against any real row (<= 95^2 + 95^2 = 18050).
    int best = -1;
    for (int p = tid; p < HW; p += 256) {
        if (!s_src[p]) continue;
        const int i = p / WD;
        const int j = p - i * WD;
        int m = 0x7fffffff;
        #pragma unroll 8
        for (int ii = 0; ii < HD; ii++) {
            int di = i - ii;
            m = min(m, di * di + (int)s_rd2[ii * WD + j]);
        }
        best = max(best, m);
    }
    s_red[tid] = best;
    __syncthreads();
    #pragma unroll
    for (int st = 128; st > 0; st >>= 1) {
        if (tid < st) s_red[tid] = max(s_red[tid], s_red[tid + st]);
        __syncthreads();
    }

    if (tid == 0) {
        float r;
        if (s_red[0] < 0)       r = 0.0f;          // empty source set
        else if (!s_anyTgt)     r = 1e9f;          // nonempty src, empty target
        else                    r = sqrtf((float)s_red[0]) * (1.0f / 96.0f);
        g_dir[s * 2 + dir] = r;
    }
}

__global__ void hausdorff_final_kernel(float* __restrict__ out, int n) {
    float acc = 0.0f;
    for (int s = 0; s < n; s++)
        acc += fmaxf(g_dir[2 * s], g_dir[2 * s + 1]);
    out[0] = acc / (float)n;
}

extern "C" void kernel_launch(void* const* d_in, const int* in_sizes, int n_in,
                              void* d_out, int out_size) {
    const float* pred = (const float*)d_in[0];
    const float* targ = (const float*)d_in[1];
    float* out = (float*)d_out;
    int n = in_sizes[0] / HW;   // batch size (8)

    dim3 grid(n, 2);
    hausdorff_dir_kernel<<<grid, 256>>>(pred, targ);
    hausdorff_final_kernel<<<1, 1>>>(out, n);
}